// round 17
// baseline (speedup 1.0000x reference)
#include <cuda_runtime.h>
#include <cuda_bf16.h>
#include <cstdint>

// B=2, C=128, IC=64, W=H=32, Z=128, nz=64. 2048 tiles of x[C=128][Z=128].
// R16 = R14 (bf16 m16n8k16 + ldmatrix + folded a[z]) with GEMM3 reoriented:
//   GEMM1 D1[o=128][z=128] = Wgp[o][Ci] @ x[Ci][z]   (g rows 0..63, phi 64..127)
//   epi1: pool z-pairs in-register; g -> gp[c][j]/64 bf16, phi -> bb partials
//   GEMM2 D2[z][c=64] = f @ gp (f bf16), y in place (bf16)
//   GEMM3' D3[Co=128][z=128] = Ww @ y^T  -> z-pairs contiguous per thread
//   epi3: out = D3*alpha + beta + x via LDG.64/STG.64 (half the memory instr)

#define N_TILES 2048
#define THREADS 256

__device__ __forceinline__ uint32_t pkbf(float lo, float hi) {
    uint32_t r;
    asm("cvt.rn.bf16x2.f32 %0, %1, %2;" : "=r"(r) : "f"(hi), "f"(lo));
    return r;
}
__device__ __forceinline__ void mma16(float* d, uint32_t a0, uint32_t a1, uint32_t a2,
                                      uint32_t a3, uint32_t b0, uint32_t b1) {
    asm volatile("mma.sync.aligned.m16n8k16.row.col.f32.bf16.bf16.f32 "
                 "{%0,%1,%2,%3}, {%4,%5,%6,%7}, {%8,%9}, {%0,%1,%2,%3};"
                 : "+f"(d[0]), "+f"(d[1]), "+f"(d[2]), "+f"(d[3])
                 : "r"(a0), "r"(a1), "r"(a2), "r"(a3), "r"(b0), "r"(b1));
}
__device__ __forceinline__ void ldsm4(uint32_t& r0, uint32_t& r1, uint32_t& r2,
                                      uint32_t& r3, uint32_t addr) {
    asm volatile("ldmatrix.sync.aligned.m8n8.x4.shared.b16 {%0,%1,%2,%3}, [%4];"
                 : "=r"(r0), "=r"(r1), "=r"(r2), "=r"(r3) : "r"(addr));
}

// ---- precomputed globals ----
__device__ float d_vt[128];      // cat_w[:64]^T @ theta_w (theta conv collapsed)
__device__ float d_ct;
__device__ float d_alpha[128];
__device__ float d_beta[128];
__device__ __align__(16) uint32_t d_A1f[8192];  // Wgp bf16 frags [strip8][ks8][lane32][r4]
__device__ __align__(16) uint32_t d_WwA[4096];  // Ww bf16 A-frags [strip8][ks4][lane32][r4]

__global__ void setup_kernel(const float* __restrict__ theta_w,
                             const float* __restrict__ theta_b,
                             const float* __restrict__ cat_w,
                             const float* __restrict__ W_b,
                             const float* __restrict__ bn_g,
                             const float* __restrict__ bn_b,
                             const float* __restrict__ bn_m,
                             const float* __restrict__ bn_v,
                             const float* __restrict__ g_w,
                             const float* __restrict__ phi_w,
                             const float* __restrict__ W_w)
{
    int tid = threadIdx.x;  // 256
    if (tid < 128) {
        float s = 0.f;
        for (int ic = 0; ic < 64; ic++) s += cat_w[ic] * theta_w[ic * 128 + tid];
        d_vt[tid] = s;
        float a = bn_g[tid] * rsqrtf(bn_v[tid] + 1e-5f);
        d_alpha[tid] = a;
        d_beta[tid]  = (W_b[tid] - bn_m[tid]) * a + bn_b[tid];
    }
    if (tid == 0) {
        float s = 0.f;
        for (int ic = 0; ic < 64; ic++) s += cat_w[ic] * theta_b[ic];
        d_ct = s;
    }
    // A frags GEMM1 (m16n8k16): a0:(row,2q..) a1:(row+8) a2:(row,2q+8) a3:(row+8,2q+8)
    for (int idx = tid; idx < 8192; idx += 256) {
        int r = idx & 3, lane = (idx >> 2) & 31, ks = (idx >> 7) & 7, s = idx >> 10;
        int l4 = lane >> 2, q = lane & 3;
        int o  = s * 16 + l4 + (r & 1) * 8;
        int ci = ks * 16 + 2 * q + ((r >> 1) & 1) * 8;
        float v0 = (o < 64) ? g_w[o * 128 + ci]     : phi_w[(o - 64) * 128 + ci];
        float v1 = (o < 64) ? g_w[o * 128 + ci + 1] : phi_w[(o - 64) * 128 + ci + 1];
        d_A1f[idx] = pkbf(v0, v1);
    }
    // A frags GEMM3' (Ww as M=Co x K=c row-major): strip s = ch*4+mt (Co block 16)
    for (int idx = tid; idx < 4096; idx += 256) {
        int r = idx & 3, lane = (idx >> 2) & 31, ks = (idx >> 7) & 3, s = idx >> 9;
        int l4 = lane >> 2, q = lane & 3;
        int Co = (s >> 2) * 64 + (s & 3) * 16 + l4 + (r & 1) * 8;
        int c  = ks * 16 + 2 * q + ((r >> 1) & 1) * 8;
        d_WwA[idx] = pkbf(W_w[Co * 64 + c], W_w[Co * 64 + c + 1]);
    }
}

// ---- smem layout (BYTE offsets) ----
#define XT_B   0       // xT bf16 [z=128][272B]  (overlaid by f/y bf16 [z=128][144B])
#define F_B    0
#define GP_B   34816   // gp bf16 [c=64][144B]
#define AS_B   44032   // a partials fp32 [8][128]
#define BBW_B  48128   // bb partials fp32 [2][64]
#define GB_B   48640
#define PB_B   48896
#define WP_B   49152
#define AL_B   49408
#define BE_B   49920
#define SMEM_BYTES 50432

__global__ void __launch_bounds__(THREADS, 2)
nonlocal_kernel(const float* __restrict__ x,
                const float* __restrict__ g_b,
                const float* __restrict__ phi_b,
                const float* __restrict__ cat_w,
                float* __restrict__ out)
{
    extern __shared__ char smc[];
    float* AS  = (float*)(smc + AS_B);
    float* BBW = (float*)(smc + BBW_B);
    float* GB  = (float*)(smc + GB_B);
    float* PB  = (float*)(smc + PB_B);
    float* WP  = (float*)(smc + WP_B);
    float* AL  = (float*)(smc + AL_B);
    float* BE  = (float*)(smc + BE_B);

    const int tid  = threadIdx.x;
    const int lane = tid & 31;
    const int wid  = tid >> 5;     // 0..7
    const int q    = lane & 3;
    const int l4   = lane >> 2;
    const int brow = lane & 7;
    const int bs1  = (lane >> 3) & 1;
    const int bs2  = (lane >> 4) & 1;

    const int n  = blockIdx.x;
    const int b  = n >> 10;
    const int wh = n & 1023;
    const size_t gbase = (size_t)b * 16777216 + (size_t)wh * 128;  // + Ci*131072 + z
    const float* xg = x + gbase;

    // ---- stage A: load x transposed -> bf16 xT[z][Ci]; fold a[z] partials ----
    {
        float4 vt4[4];
        #pragma unroll
        for (int k = 0; k < 4; k++) vt4[k] = ((const float4*)d_vt)[wid * 4 + k];
        float ap[4] = {0.f, 0.f, 0.f, 0.f};
        #pragma unroll
        for (int it = 0; it < 16; it++) {
            int g = wid * 16 + it;
            int c0 = 4 * (g >> 2), zsel = g & 3;
            int z = 32 * zsel + lane;
            float v0 = xg[(size_t)(c0 + 0) * 131072 + z];
            float v1 = xg[(size_t)(c0 + 1) * 131072 + z];
            float v2 = xg[(size_t)(c0 + 2) * 131072 + z];
            float v3 = xg[(size_t)(c0 + 3) * 131072 + z];
            *(uint2*)(smc + XT_B + z * 272 + 2 * c0) = make_uint2(pkbf(v0, v1), pkbf(v2, v3));
            float4 w = vt4[it >> 2];
            ap[zsel] = fmaf(w.x, v0, fmaf(w.y, v1, fmaf(w.z, v2, fmaf(w.w, v3, ap[zsel]))));
        }
        #pragma unroll
        for (int zsel = 0; zsel < 4; zsel++)
            AS[wid * 128 + 32 * zsel + lane] = ap[zsel];
    }
    if (tid < 128) { AL[tid] = d_alpha[tid]; BE[tid] = d_beta[tid]; }
    if (tid < 64)  { GB[tid] = g_b[tid]; PB[tid] = phi_b[tid]; WP[tid] = cat_w[64 + tid]; }
    __syncthreads();

    // ---- GEMM1: warp grid 4 o-strips(32) x 2 z-halves(64); K=128, 8 ks ----
    const int oz = wid & 3;
    const int zh = wid >> 2;
    const int zb = zh * 64;

    float d1[2][8][4];
    #pragma unroll
    for (int mt = 0; mt < 2; mt++)
        #pragma unroll
        for (int nt = 0; nt < 8; nt++)
            #pragma unroll
            for (int r = 0; r < 4; r++) d1[mt][nt][r] = 0.f;

    {
        const uint4* gA0 = ((const uint4*)d_A1f) + (oz * 2) * 256;
        const uint4* gA1 = gA0 + 256;
        uint32_t xb = (uint32_t)__cvta_generic_to_shared(smc + XT_B)
                    + (uint32_t)((zb + bs2 * 8 + brow) * 272 + bs1 * 16);
        uint4 af0 = gA0[lane], af1 = gA1[lane];
        #pragma unroll 1
        for (int ks = 0; ks < 8; ks++) {
            uint4 c0 = af0, c1 = af1;
            if (ks < 7) { af0 = gA0[(ks + 1) * 32 + lane]; af1 = gA1[(ks + 1) * 32 + lane]; }
            #pragma unroll
            for (int ntp = 0; ntp < 4; ntp++) {
                uint32_t b0, b1, b2, b3;
                ldsm4(b0, b1, b2, b3, xb + (uint32_t)(ntp * 16 * 272 + 32 * ks));
                mma16(d1[0][2 * ntp],     c0.x, c0.y, c0.z, c0.w, b0, b1);
                mma16(d1[0][2 * ntp + 1], c0.x, c0.y, c0.z, c0.w, b2, b3);
                mma16(d1[1][2 * ntp],     c1.x, c1.y, c1.z, c1.w, b0, b1);
                mma16(d1[1][2 * ntp + 1], c1.x, c1.y, c1.z, c1.w, b2, b3);
            }
        }
    }
    __syncthreads();   // xT reads done -> overlay writable

    // ---- epi1: pool z-pairs; g -> gp bf16 [c][j], phi -> bb partials ----
    if (oz < 2) {
        #pragma unroll
        for (int mt = 0; mt < 2; mt++) {
            const int o0 = oz * 32 + 16 * mt + l4, o1 = o0 + 8;
            const float gb0 = GB[o0], gb1 = GB[o1];
            #pragma unroll
            for (int nt = 0; nt < 8; nt++) {
                int j = zb / 2 + 4 * nt + q;
                float g0 = (fmaxf(d1[mt][nt][0], d1[mt][nt][1]) + gb0) * 0.015625f;
                float g1 = (fmaxf(d1[mt][nt][2], d1[mt][nt][3]) + gb1) * 0.015625f;
                *(__nv_bfloat16*)(smc + GP_B + o0 * 144 + 2 * j) = __float2bfloat16(g0);
                *(__nv_bfloat16*)(smc + GP_B + o1 * 144 + 2 * j) = __float2bfloat16(g1);
            }
        }
    } else {
        #pragma unroll
        for (int nt = 0; nt < 8; nt++) {
            float v = 0.f;
            #pragma unroll
            for (int mt = 0; mt < 2; mt++) {
                const int p0 = (oz - 2) * 32 + 16 * mt + l4, p1 = p0 + 8;
                v += WP[p0] * (fmaxf(d1[mt][nt][0], d1[mt][nt][1]) + PB[p0])
                   + WP[p1] * (fmaxf(d1[mt][nt][2], d1[mt][nt][3]) + PB[p1]);
            }
            v += __shfl_xor_sync(0xFFFFFFFFu, v, 16);
            v += __shfl_xor_sync(0xFFFFFFFFu, v, 8);
            v += __shfl_xor_sync(0xFFFFFFFFu, v, 4);
            if (l4 == 0) BBW[(oz - 2) * 64 + zb / 2 + 4 * nt + q] = v;
        }
    }
    __syncthreads();

    {   // f[z][j] = relu(a[z] + bb[j]) -> bf16; a = ct + 8 group partials
        const int z = tid >> 1, half = tid & 1;
        float az = d_ct;
        #pragma unroll
        for (int g = 0; g < 8; g++) az += AS[g * 128 + z];
        #pragma unroll
        for (int jj = 0; jj < 8; jj++) {
            int j = half * 32 + 4 * jj;
            float f0 = fmaxf(az + BBW[j + 0] + BBW[64 + j + 0], 0.f);
            float f1 = fmaxf(az + BBW[j + 1] + BBW[64 + j + 1], 0.f);
            float f2 = fmaxf(az + BBW[j + 2] + BBW[64 + j + 2], 0.f);
            float f3 = fmaxf(az + BBW[j + 3] + BBW[64 + j + 3], 0.f);
            *(uint2*)(smc + F_B + z * 144 + 2 * j) = make_uint2(pkbf(f0, f1), pkbf(f2, f3));
        }
    }
    __syncthreads();

    // ---- GEMM2: D2[z][c] = f @ gp; warp = z-strip 16 (wid); K=64, 4 ks ----
    {
        float d2[8][4];
        #pragma unroll
        for (int nt = 0; nt < 8; nt++)
            #pragma unroll
            for (int r = 0; r < 4; r++) d2[nt][r] = 0.f;

        uint32_t fa = (uint32_t)__cvta_generic_to_shared(smc + F_B)
                    + (uint32_t)((16 * wid + bs1 * 8 + brow) * 144 + bs2 * 16);
        uint32_t gb_ = (uint32_t)__cvta_generic_to_shared(smc + GP_B)
                    + (uint32_t)((bs2 * 8 + brow) * 144 + bs1 * 16);
        #pragma unroll 1
        for (int ks = 0; ks < 4; ks++) {
            uint32_t a0, a1, a2, a3;
            ldsm4(a0, a1, a2, a3, fa + (uint32_t)(32 * ks));
            #pragma unroll
            for (int ntp = 0; ntp < 4; ntp++) {
                uint32_t b0, b1, b2, b3;
                ldsm4(b0, b1, b2, b3, gb_ + (uint32_t)(ntp * 16 * 144 + 32 * ks));
                mma16(d2[2 * ntp],     a0, a1, a2, a3, b0, b1);
                mma16(d2[2 * ntp + 1], a0, a1, a2, a3, b2, b3);
            }
        }
        __syncthreads();   // gp reads done; f strip rewrite below is warp-local
        // epi2: y (bf16) overwrites own f strip
        #pragma unroll
        for (int nt = 0; nt < 8; nt++) {
            int cbyte = 2 * (8 * nt + 2 * q);
            *(uint32_t*)(smc + F_B + (16 * wid + l4) * 144 + cbyte)     = pkbf(d2[nt][0], d2[nt][1]);
            *(uint32_t*)(smc + F_B + (16 * wid + l4 + 8) * 144 + cbyte) = pkbf(d2[nt][2], d2[nt][3]);
        }
    }
    __syncthreads();   // y read cross-warp in GEMM3'

    // ---- GEMM3': D3[Co][z] = Ww @ y^T; warp grid 2 Co-halves x 4 z-strips(32) ----
    {
        const int ch  = wid & 1;        // Co half (64)
        const int zq3 = wid >> 1;       // z strip of 32
        const int zb3 = zq3 * 32;

        float d3[4][4][4];              // [mt Co-strip16][nt z-tile8][4]
        #pragma unroll
        for (int mt = 0; mt < 4; mt++)
            #pragma unroll
            for (int nt = 0; nt < 4; nt++)
                #pragma unroll
                for (int r = 0; r < 4; r++) d3[mt][nt][r] = 0.f;

        // B = y rows (n=z, k=c): same ldsm pattern as GEMM1's B
        uint32_t yb = (uint32_t)__cvta_generic_to_shared(smc + F_B)
                    + (uint32_t)((zb3 + bs2 * 8 + brow) * 144 + bs1 * 16);
        const uint4* gA = ((const uint4*)d_WwA) + (ch * 4) * 128;  // 4 mt strips, 4 ks each
        #pragma unroll 1
        for (int ks = 0; ks < 4; ks++) {
            uint32_t b00, b01, b02, b03, b10, b11, b12, b13;
            ldsm4(b00, b01, b02, b03, yb + (uint32_t)(32 * ks));             // z tiles 0,1
            ldsm4(b10, b11, b12, b13, yb + (uint32_t)(16 * 144 + 32 * ks));  // z tiles 2,3
            #pragma unroll
            for (int mt = 0; mt < 4; mt++) {
                uint4 a = gA[(mt * 4 + ks) * 32 + lane];
                mma16(d3[mt][0], a.x, a.y, a.z, a.w, b00, b01);
                mma16(d3[mt][1], a.x, a.y, a.z, a.w, b02, b03);
                mma16(d3[mt][2], a.x, a.y, a.z, a.w, b10, b11);
                mma16(d3[mt][3], a.x, a.y, a.z, a.w, b12, b13);
            }
        }

        // ---- epi3: out = D3*alpha + beta + x ; z-pairs contiguous -> .64 ops ----
        #pragma unroll
        for (int mt = 0; mt < 4; mt++) {
            const int Co0 = ch * 64 + mt * 16 + l4, Co1 = Co0 + 8;
            const float al0 = AL[Co0], be0 = BE[Co0];
            const float al1 = AL[Co1], be1 = BE[Co1];
            const size_t r0 = gbase + (size_t)Co0 * 131072;
            const size_t r1 = gbase + (size_t)Co1 * 131072;
            #pragma unroll
            for (int nt = 0; nt < 4; nt++) {
                const int z = zb3 + 8 * nt + 2 * q;
                float2 xv0 = *(const float2*)(x + r0 + z);
                float2 xv1 = *(const float2*)(x + r1 + z);
                float2 o0, o1;
                o0.x = fmaf(d3[mt][nt][0], al0, be0) + xv0.x;
                o0.y = fmaf(d3[mt][nt][1], al0, be0) + xv0.y;
                o1.x = fmaf(d3[mt][nt][2], al1, be1) + xv1.x;
                o1.y = fmaf(d3[mt][nt][3], al1, be1) + xv1.y;
                *(float2*)(out + r0 + z) = o0;
                *(float2*)(out + r1 + z) = o1;
            }
        }
    }
}

extern "C" void kernel_launch(void* const* d_in, const int* in_sizes, int n_in,
                              void* d_out, int out_size)
{
    const float* x       = (const float*)d_in[0];
    const float* g_w     = (const float*)d_in[1];
    const float* g_b     = (const float*)d_in[2];
    const float* theta_w = (const float*)d_in[3];
    const float* theta_b = (const float*)d_in[4];
    const float* phi_w   = (const float*)d_in[5];
    const float* phi_b   = (const float*)d_in[6];
    const float* cat_w   = (const float*)d_in[7];
    const float* W_w     = (const float*)d_in[8];
    const float* W_b     = (const float*)d_in[9];
    const float* bn_g    = (const float*)d_in[10];
    const float* bn_b    = (const float*)d_in[11];
    const float* bn_m    = (const float*)d_in[12];
    const float* bn_v    = (const float*)d_in[13];

    cudaFuncSetAttribute(nonlocal_kernel,
                         cudaFuncAttributeMaxDynamicSharedMemorySize, SMEM_BYTES);

    setup_kernel<<<1, 256>>>(theta_w, theta_b, cat_w, W_b,
                             bn_g, bn_b, bn_m, bn_v, g_w, phi_w, W_w);
    nonlocal_kernel<<<N_TILES, THREADS, SMEM_BYTES>>>(x, g_b, phi_b, cat_w,
                                                      (float*)d_out);
}